// round 8
// baseline (speedup 1.0000x reference)
#include <cuda_runtime.h>
#include <math.h>

#define NSTEPS 8760
#define NGRID  2048
#define NMUL   2
#define NTID   (NGRID*NMUL)
#define LENF   72
#define DTC    (1.0f/24.0f)
#define NBLK   (NSTEPS/4)        /* 2190 four-step blocks; 2190 = 3*730 */

// Scratch (device globals: no allocation allowed in kernel_launch)
__device__ float g_q2[NSTEPS * NTID];   // per-(t, grid, mul) discharge [t][tid]
__device__ float g_w[LENF * NGRID];     // gamma weights [k][g]

__device__ __forceinline__ float flg2(float x) {
    float y; asm("lg2.approx.f32 %0, %1;" : "=f"(y) : "f"(x)); return y;
}
__device__ __forceinline__ float fex2(float x) {
    float y; asm("ex2.approx.f32 %0, %1;" : "=f"(y) : "f"(x)); return y;
}

// ---------------------------------------------------------------------------
// Stage 1: HBV scan. One thread per (grid, mul); 4096 threads, one warp per
// SM on 128 SMs. Instruction-dieted step (~52 SASS instrs/step), MOV-free
// triple-buffered forcing prefetch (12-step outer unroll, lookahead 8 steps).
// ---------------------------------------------------------------------------
__global__ void __launch_bounds__(32) hbv_scan_kernel(
    const float* __restrict__ prcp,
    const float* __restrict__ tmean,
    const float* __restrict__ pet,
    const float* __restrict__ phy)
{
    const int tid = blockIdx.x * 32 + threadIdx.x;   // 0..4095
    const int g = tid >> 1;
    const int m = tid & 1;

    const float lbv[19] = {1.0f, 50.0f, 0.05f, 0.01f, 0.001f, 0.2f, 0.0f, 0.0f,
                           -2.5f, 0.5f, 0.0f, 0.0f, 0.3f, 0.0f, 0.0f, 0.0f,
                           5.0f/DTC, 0.0f, 0.5f};
    const float ubv[19] = {6.0f, 1000.0f, 0.9f, 0.5f, 0.2f, 1.0f, 10.0f, 100.0f,
                           2.5f, 10.0f, 0.1f, 0.2f, 5.0f, 1.0f, 20.0f, 2500.0f,
                           120.0f/DTC, 1.0f, 5.0f};
    float pp[19];
#pragma unroll
    for (int i = 0; i < 19; i++) {
        float r = phy[g * (19 * NMUL) + i * NMUL + m];
        pp[i] = lbv[i] + r * (ubv[i] - lbv[i]);
    }
    const float BETA   = pp[0];
    const float FC     = pp[1];
    const float CFR    = pp[10];
    const float CWH    = pp[11];
    const float BETAET = pp[12];
    const float Cc     = pp[13];
    const float ALPHA  = pp[18];

    const float invFC       = 1.0f / FC;
    const float k0dt        = pp[2] * DTC;
    const float k1dt        = pp[3] * DTC;
    const float k2dt        = pp[4] * DTC;
    const float percdt      = pp[6] * DTC;
    const float cfmaxdt     = pp[9] * DTC;
    const float f0dt        = pp[16] * DTC;
    const float fmin_f0dt   = pp[17] * f0dt;
    const float omfmin_f0dt = (1.0f - pp[17]) * f0dt;
    const float evap_c      = BETAET * flg2(1.0f / (pp[5] * FC));
    const float eFCc        = fminf(fex2(BETAET * flg2(1.0f / pp[5])), 1.0f);
    const float mpc         = cfmaxdt * pp[8];   // cfmaxdt*TT
    const float ck0         = 1.0f - k0dt;
    const float k0uzl       = k0dt * pp[7];
    const float c1          = 1.0f - k1dt;
    const float c2          = 1.0f - k2dt;
    const float cc2         = Cc * c2;

    float SP = 0.001f, MW = 0.001f, SM = 0.001f, SUZ = 0.001f, SLZ = 0.001f;
    float CcSLZ = Cc * 0.001f;

    auto step = [&](float P, float T, float PV) -> float {
        // --- snow: fused signed transfer x = melt - refreeze
        // s2 = max(mp, CFR*mp): mp if mp>=0 (melt), CFR*mp if mp<0 (-refreeze)
        float mp   = fmaf(cfmaxdt, T, -mpc);           // cfmaxdt*(T-TT)
        float RAIN = (mp >= 0.0f) ? P : 0.0f;
        float SP1  = (SP + P) - RAIN;                  // SP + SNOW
        float s2   = fmaxf(mp, CFR * mp);
        float x    = fminf(fmaxf(s2, -MW), SP1);
        SP = SP1 - x;
        float MW2    = MW + x;
        float tosoil = fmaxf(fmaf(-CWH, SP, MW2), 0.0f);
        MW = MW2 - tosoil;
        float win = RAIN + tosoil;

        // --- soil moisture (critical carry cycle)
        float omr   = fmaxf(fmaf(-invFC, SM, 1.0f), 1e-6f);
        float fcap  = fmaf(omfmin_f0dt, fex2(ALPHA * flg2(omr)), fmin_f0dt);
        float infil = fminf(win, fcap);
        float ratio = SM * invFC;
        float soilw = fminf(fex2(BETA * flg2(ratio)), 1.0f);
        float SM1   = fmaf(infil, 1.0f - soilw, SM);
        float SM2   = fminf(SM1, FC);
        float e1    = fex2(fmaf(flg2(SM1), BETAET, evap_c));  // e_raw(SM1)
        float xe    = fminf(PV * e1, PV * eFCc);              // PV*e(SM2), clipped
        float SM3   = fmaxf(SM2 - xe, 1e-5f);
        float w1    = fmaf(-invFC, SM3, 1.0f);
        float cap   = CcSLZ * w1;
        float inflow = (SM - SM2) + win;     // == rech + excs + surf (exact algebra)
        SM = SM3 + cap;

        // --- zones (compressed)
        float SUZ1 = SUZ + inflow;
        float SUZ2 = fmaxf(SUZ1 - percdt, 0.0f);
        float perc = SUZ1 - SUZ2;
        float SUZ3 = fminf(SUZ2, fmaf(ck0, SUZ2, k0uzl));
        float SUZn = c1 * SUZ3;
        SUZ = SUZn;
        float SLZ1 = (SLZ - cap) + perc;
        float Q2   = k2dt * SLZ1;
        SLZ   = c2 * SLZ1;
        CcSLZ = cc2 * SLZ1;
        return (SUZ2 - SUZn) + Q2;           // Q0+Q1+Q2
    };

    // triple-buffered forcing: 4-step blocks, unroll-3 (MOV-free rotation),
    // prefetch lookahead = 2 blocks (8 steps).
    float Pf[3][4], Tf[3][4], Ef[3][4];
#pragma unroll
    for (int s = 0; s < 2; s++)
#pragma unroll
        for (int u = 0; u < 4; u++) {
            Pf[s][u] = prcp [(s * 4 + u) * NGRID + g];
            Tf[s][u] = tmean[(s * 4 + u) * NGRID + g];
            Ef[s][u] = pet  [(s * 4 + u) * NGRID + g];
        }

    const float* pbase = prcp  + g;
    const float* tbase = tmean + g;
    const float* ebase = pet   + g;
    float*       qp    = g_q2  + tid;

    int blk = 0;
    for (int it = 0; it < NBLK / 3; it++) {
#pragma unroll
        for (int s = 0; s < 3; s++) {
            const int ps = (s + 2) % 3;          // slot consumed 2 blocks ago
            const int pb = min(blk + 2, NBLK - 1);
            const float* pa = pbase + (size_t)pb * (4 * NGRID);
            const float* ta = tbase + (size_t)pb * (4 * NGRID);
            const float* ea = ebase + (size_t)pb * (4 * NGRID);
#pragma unroll
            for (int u = 0; u < 4; u++) {
                Pf[ps][u] = pa[u * NGRID];
                Tf[ps][u] = ta[u * NGRID];
                Ef[ps][u] = ea[u * NGRID];
            }
#pragma unroll
            for (int u = 0; u < 4; u++)
                qp[(size_t)u * NTID] = step(Pf[s][u], Tf[s][u], Ef[s][u]);
            qp += 4 * NTID;
            blk++;
        }
    }
}

// ---------------------------------------------------------------------------
// Stage 2: gamma routing weights, one thread per grid.
// ---------------------------------------------------------------------------
__global__ void __launch_bounds__(128) weights_kernel(const float* __restrict__ distr)
{
    int g = blockIdx.x * blockDim.x + threadIdx.x;
    if (g >= NGRID) return;

    float aa  = fmaxf(distr[g * 3 + 0] * 5.0f,  0.0f) + 0.1f;
    float th  = fmaxf(distr[g * 3 + 1] * 12.0f, 0.0f) + 0.5f;
    float tau = distr[g * 3 + 2] * 48.0f;

    float lga   = lgammaf(aa);
    float lth   = logf(th);
    float invth = 1.0f / th;
    float am1   = aa - 1.0f;

    float ws[LENF];
    float s = 0.0f;
#pragma unroll
    for (int k = 0; k < LENF; k++) {
        float t  = (float)k + 0.5f;
        float ts = fmaxf(t - tau, 0.001f);
        float lw = -lga - aa * lth + am1 * logf(ts) - ts * invth;
        float w  = expf(lw);
        ws[k] = w;
        s += w;
    }
    float inv = 1.0f / s;
#pragma unroll
    for (int k = 0; k < LENF; k++)
        g_w[k * NGRID + g] = ws[k] * inv;
}

// ---------------------------------------------------------------------------
// Stage 3: 72-tap causal FIR. Tile 32 grids x 128 timesteps; 16 outputs per
// thread, mod-16 register rolling window. Mul pair averaged at load (float2).
// ---------------------------------------------------------------------------
#define CONV_GT   32
#define CONV_TT   128
#define CONV_RPT  16
#define CONV_QS   (CONV_TT + LENF - 1)   /* 199 */

__global__ void __launch_bounds__(256) conv_kernel(float* __restrict__ out)
{
    __shared__ float q_sh[CONV_QS][CONV_GT];   // 199 x 32
    __shared__ float w_sh[LENF][CONV_GT];      // 72 x 32

    const int tid   = threadIdx.x;
    const int gbase = blockIdx.x * CONV_GT;
    const int t0    = blockIdx.y * CONV_TT;

    const float2* q2 = reinterpret_cast<const float2*>(g_q2);

    for (int idx = tid; idx < CONV_QS * CONV_GT; idx += 256) {
        int j = idx >> 5, c = idx & 31;
        int tq = t0 - (LENF - 1) + j;
        float v = 0.0f;
        if (tq >= 0 && tq < NSTEPS) {
            float2 p = q2[(size_t)tq * NGRID + gbase + c];
            v = 0.5f * (p.x + p.y);
        }
        q_sh[j][c] = v;
    }
    for (int idx = tid; idx < LENF * CONV_GT; idx += 256) {
        int k = idx >> 5, c = idx & 31;
        w_sh[k][c] = g_w[k * NGRID + gbase + c];
    }
    __syncthreads();

    const int tx   = tid & 31;
    const int ty   = tid >> 5;        // 0..7
    const int trow = ty * CONV_RPT;

    float acc[CONV_RPT];
#pragma unroll
    for (int r = 0; r < CONV_RPT; r++) acc[r] = 0.0f;

    float buf[16];                    // mod-16 register rolling window
#pragma unroll
    for (int i = 0; i < 16; i++)
        buf[(LENF - 1 + i) & 15] = q_sh[trow + LENF - 1 + i][tx];

#pragma unroll
    for (int k = 0; k < LENF; k++) {
        float wv = w_sh[k][tx];
#pragma unroll
        for (int r = 0; r < CONV_RPT; r++)
            acc[r] += wv * buf[(LENF - 1 - k + r) & 15];
        if (k < LENF - 1)
            buf[(LENF - 2 - k) & 15] = q_sh[trow + LENF - 2 - k][tx];
    }

#pragma unroll
    for (int r = 0; r < CONV_RPT; r++) {
        int t = t0 + trow + r;
        if (t < NSTEPS)
            out[t * NGRID + gbase + tx] = acc[r];
    }
}

// ---------------------------------------------------------------------------
extern "C" void kernel_launch(void* const* d_in, const int* in_sizes, int n_in,
                              void* d_out, int out_size)
{
    const float* prcp  = (const float*)d_in[0];
    const float* tmean = (const float*)d_in[1];
    const float* pet   = (const float*)d_in[2];
    const float* phy   = (const float*)d_in[3];
    const float* distr = (const float*)d_in[4];
    float* out = (float*)d_out;

    hbv_scan_kernel<<<NTID / 32, 32>>>(prcp, tmean, pet, phy);
    weights_kernel<<<(NGRID + 127) / 128, 128>>>(distr);

    dim3 gc(NGRID / CONV_GT, (NSTEPS + CONV_TT - 1) / CONV_TT);
    conv_kernel<<<gc, 256>>>(out);
}

// round 9
// speedup vs baseline: 1.5242x; 1.5242x over previous
#include <cuda_runtime.h>
#include <math.h>

#define NSTEPS 8760
#define NGRID  2048
#define NMUL   2
#define NTID   (NGRID*NMUL)
#define LENF   72
#define DTC    (1.0f/24.0f)

// Scratch (device globals: no allocation allowed in kernel_launch)
__device__ float g_q2[NSTEPS * NTID];   // per-(t, grid, mul) discharge [t][tid]
__device__ float g_w[LENF * NGRID];     // gamma weights [k][g]

__device__ __forceinline__ float flg2(float x) {
    float y; asm("lg2.approx.f32 %0, %1;" : "=f"(y) : "f"(x)); return y;
}
__device__ __forceinline__ float fex2(float x) {
    float y; asm("ex2.approx.f32 %0, %1;" : "=f"(y) : "f"(x)); return y;
}

// ---------------------------------------------------------------------------
// Stage 1: HBV scan. One thread per (grid, mul); 4096 threads in 32 blocks of
// 128 (the empirically fast config). R8 instruction-dieted step body inside
// the R7 U=8 double-buffered loop skeleton.
// ---------------------------------------------------------------------------
__global__ void __launch_bounds__(128) hbv_scan_kernel(
    const float* __restrict__ prcp,
    const float* __restrict__ tmean,
    const float* __restrict__ pet,
    const float* __restrict__ phy)
{
    const int tid = blockIdx.x * 128 + threadIdx.x;   // 0..4095
    const int g = tid >> 1;
    const int m = tid & 1;

    const float lbv[19] = {1.0f, 50.0f, 0.05f, 0.01f, 0.001f, 0.2f, 0.0f, 0.0f,
                           -2.5f, 0.5f, 0.0f, 0.0f, 0.3f, 0.0f, 0.0f, 0.0f,
                           5.0f/DTC, 0.0f, 0.5f};
    const float ubv[19] = {6.0f, 1000.0f, 0.9f, 0.5f, 0.2f, 1.0f, 10.0f, 100.0f,
                           2.5f, 10.0f, 0.1f, 0.2f, 5.0f, 1.0f, 20.0f, 2500.0f,
                           120.0f/DTC, 1.0f, 5.0f};
    float pp[19];
#pragma unroll
    for (int i = 0; i < 19; i++) {
        float r = phy[g * (19 * NMUL) + i * NMUL + m];
        pp[i] = lbv[i] + r * (ubv[i] - lbv[i]);
    }
    const float BETA   = pp[0];
    const float FC     = pp[1];
    const float CFR    = pp[10];
    const float CWH    = pp[11];
    const float BETAET = pp[12];
    const float Cc     = pp[13];
    const float ALPHA  = pp[18];

    const float invFC       = 1.0f / FC;
    const float k0dt        = pp[2] * DTC;
    const float k1dt        = pp[3] * DTC;
    const float k2dt        = pp[4] * DTC;
    const float percdt      = pp[6] * DTC;
    const float cfmaxdt     = pp[9] * DTC;
    const float f0dt        = pp[16] * DTC;
    const float fmin_f0dt   = pp[17] * f0dt;
    const float omfmin_f0dt = (1.0f - pp[17]) * f0dt;
    const float evap_c      = BETAET * flg2(1.0f / (pp[5] * FC));
    const float eFCc        = fminf(fex2(BETAET * flg2(1.0f / pp[5])), 1.0f);
    const float mpc         = cfmaxdt * pp[8];   // cfmaxdt*TT
    const float ck0         = 1.0f - k0dt;
    const float k0uzl       = k0dt * pp[7];
    const float c1          = 1.0f - k1dt;
    const float c2          = 1.0f - k2dt;
    const float cc2         = Cc * c2;

    float SP = 0.001f, MW = 0.001f, SM = 0.001f, SUZ = 0.001f, SLZ = 0.001f;
    float CcSLZ = Cc * 0.001f;

    auto step = [&](float P, float T, float PV) -> float {
        // --- snow: fused signed transfer x = melt - refreeze
        // s2 = max(mp, CFR*mp): mp if mp>=0 (melt), CFR*mp if mp<0 (-refreeze)
        float mp   = fmaf(cfmaxdt, T, -mpc);           // cfmaxdt*(T-TT)
        float RAIN = (mp >= 0.0f) ? P : 0.0f;
        float SP1  = (SP + P) - RAIN;                  // SP + SNOW
        float s2   = fmaxf(mp, CFR * mp);
        float x    = fminf(fmaxf(s2, -MW), SP1);
        SP = SP1 - x;
        float MW2    = MW + x;
        float tosoil = fmaxf(fmaf(-CWH, SP, MW2), 0.0f);
        MW = MW2 - tosoil;
        float win = RAIN + tosoil;

        // --- soil moisture (critical carry cycle)
        float omr   = fmaxf(fmaf(-invFC, SM, 1.0f), 1e-6f);
        float fcap  = fmaf(omfmin_f0dt, fex2(ALPHA * flg2(omr)), fmin_f0dt);
        float infil = fminf(win, fcap);
        float ratio = SM * invFC;
        float soilw = fminf(fex2(BETA * flg2(ratio)), 1.0f);
        float SM1   = fmaf(infil, 1.0f - soilw, SM);
        float SM2   = fminf(SM1, FC);
        float e1    = fex2(fmaf(flg2(SM1), BETAET, evap_c));  // e_raw(SM1)
        float xe    = fminf(PV * e1, PV * eFCc);              // PV*e(SM2), clipped
        float SM3   = fmaxf(SM2 - xe, 1e-5f);
        float w1    = fmaf(-invFC, SM3, 1.0f);
        float cap   = CcSLZ * w1;
        float inflow = (SM - SM2) + win;     // == rech + excs + surf (exact)
        SM = SM3 + cap;

        // --- zones (compressed)
        float SUZ1 = SUZ + inflow;
        float SUZ2 = fmaxf(SUZ1 - percdt, 0.0f);
        float perc = SUZ1 - SUZ2;
        float SUZ3 = fminf(SUZ2, fmaf(ck0, SUZ2, k0uzl));
        float SUZn = c1 * SUZ3;
        SUZ = SUZn;
        float SLZ1 = (SLZ - cap) + perc;
        float Q2   = k2dt * SLZ1;
        SLZ   = c2 * SLZ1;
        CcSLZ = cc2 * SLZ1;
        return (SUZ2 - SUZn) + Q2;           // Q0+Q1+Q2
    };

    const int U = 8;                     // 8760 % 8 == 0
    float Pb[U], Tb[U], Eb[U];
#pragma unroll
    for (int u = 0; u < U; u++) {
        Pb[u] = prcp [u * NGRID + g];
        Tb[u] = tmean[u * NGRID + g];
        Eb[u] = pet  [u * NGRID + g];
    }

    float* qbase = g_q2 + tid;

    for (int t0 = 0; t0 < NSTEPS - U; t0 += U) {
        float Pn[U], Tn[U], En[U];
        const int t1 = t0 + U;
#pragma unroll
        for (int u = 0; u < U; u++) {
            Pn[u] = prcp [(t1 + u) * NGRID + g];
            Tn[u] = tmean[(t1 + u) * NGRID + g];
            En[u] = pet  [(t1 + u) * NGRID + g];
        }
#pragma unroll
        for (int u = 0; u < U; u++)
            qbase[(size_t)(t0 + u) * NTID] = step(Pb[u], Tb[u], Eb[u]);
#pragma unroll
        for (int u = 0; u < U; u++) { Pb[u] = Pn[u]; Tb[u] = Tn[u]; Eb[u] = En[u]; }
    }
    // peeled last block (keeps the main loop branch-free)
#pragma unroll
    for (int u = 0; u < U; u++)
        qbase[(size_t)(NSTEPS - U + u) * NTID] = step(Pb[u], Tb[u], Eb[u]);
}

// ---------------------------------------------------------------------------
// Stage 2: gamma routing weights, one thread per grid.
// ---------------------------------------------------------------------------
__global__ void __launch_bounds__(128) weights_kernel(const float* __restrict__ distr)
{
    int g = blockIdx.x * blockDim.x + threadIdx.x;
    if (g >= NGRID) return;

    float aa  = fmaxf(distr[g * 3 + 0] * 5.0f,  0.0f) + 0.1f;
    float th  = fmaxf(distr[g * 3 + 1] * 12.0f, 0.0f) + 0.5f;
    float tau = distr[g * 3 + 2] * 48.0f;

    float lga   = lgammaf(aa);
    float lth   = logf(th);
    float invth = 1.0f / th;
    float am1   = aa - 1.0f;

    float ws[LENF];
    float s = 0.0f;
#pragma unroll
    for (int k = 0; k < LENF; k++) {
        float t  = (float)k + 0.5f;
        float ts = fmaxf(t - tau, 0.001f);
        float lw = -lga - aa * lth + am1 * logf(ts) - ts * invth;
        float w  = expf(lw);
        ws[k] = w;
        s += w;
    }
    float inv = 1.0f / s;
#pragma unroll
    for (int k = 0; k < LENF; k++)
        g_w[k * NGRID + g] = ws[k] * inv;
}

// ---------------------------------------------------------------------------
// Stage 3: 72-tap causal FIR. Tile 32 grids x 128 timesteps; 16 outputs per
// thread, mod-16 register rolling window. Mul pair averaged at load (float2).
// ---------------------------------------------------------------------------
#define CONV_GT   32
#define CONV_TT   128
#define CONV_RPT  16
#define CONV_QS   (CONV_TT + LENF - 1)   /* 199 */

__global__ void __launch_bounds__(256) conv_kernel(float* __restrict__ out)
{
    __shared__ float q_sh[CONV_QS][CONV_GT];   // 199 x 32
    __shared__ float w_sh[LENF][CONV_GT];      // 72 x 32

    const int tid   = threadIdx.x;
    const int gbase = blockIdx.x * CONV_GT;
    const int t0    = blockIdx.y * CONV_TT;

    const float2* q2 = reinterpret_cast<const float2*>(g_q2);

    for (int idx = tid; idx < CONV_QS * CONV_GT; idx += 256) {
        int j = idx >> 5, c = idx & 31;
        int tq = t0 - (LENF - 1) + j;
        float v = 0.0f;
        if (tq >= 0 && tq < NSTEPS) {
            float2 p = q2[(size_t)tq * NGRID + gbase + c];
            v = 0.5f * (p.x + p.y);
        }
        q_sh[j][c] = v;
    }
    for (int idx = tid; idx < LENF * CONV_GT; idx += 256) {
        int k = idx >> 5, c = idx & 31;
        w_sh[k][c] = g_w[k * NGRID + gbase + c];
    }
    __syncthreads();

    const int tx   = tid & 31;
    const int ty   = tid >> 5;        // 0..7
    const int trow = ty * CONV_RPT;

    float acc[CONV_RPT];
#pragma unroll
    for (int r = 0; r < CONV_RPT; r++) acc[r] = 0.0f;

    float buf[16];                    // mod-16 register rolling window
#pragma unroll
    for (int i = 0; i < 16; i++)
        buf[(LENF - 1 + i) & 15] = q_sh[trow + LENF - 1 + i][tx];

#pragma unroll
    for (int k = 0; k < LENF; k++) {
        float wv = w_sh[k][tx];
#pragma unroll
        for (int r = 0; r < CONV_RPT; r++)
            acc[r] += wv * buf[(LENF - 1 - k + r) & 15];
        if (k < LENF - 1)
            buf[(LENF - 2 - k) & 15] = q_sh[trow + LENF - 2 - k][tx];
    }

#pragma unroll
    for (int r = 0; r < CONV_RPT; r++) {
        int t = t0 + trow + r;
        if (t < NSTEPS)
            out[t * NGRID + gbase + tx] = acc[r];
    }
}

// ---------------------------------------------------------------------------
extern "C" void kernel_launch(void* const* d_in, const int* in_sizes, int n_in,
                              void* d_out, int out_size)
{
    const float* prcp  = (const float*)d_in[0];
    const float* tmean = (const float*)d_in[1];
    const float* pet   = (const float*)d_in[2];
    const float* phy   = (const float*)d_in[3];
    const float* distr = (const float*)d_in[4];
    float* out = (float*)d_out;

    hbv_scan_kernel<<<NTID / 128, 128>>>(prcp, tmean, pet, phy);
    weights_kernel<<<(NGRID + 127) / 128, 128>>>(distr);

    dim3 gc(NGRID / CONV_GT, (NSTEPS + CONV_TT - 1) / CONV_TT);
    conv_kernel<<<gc, 256>>>(out);
}

// round 10
// speedup vs baseline: 1.5274x; 1.0021x over previous
#include <cuda_runtime.h>
#include <math.h>

#define NSTEPS 8760
#define NGRID  2048
#define NMUL   2
#define NTID   (NGRID*NMUL)
#define LENF   72
#define DTC    (1.0f/24.0f)

// Scratch (device globals: no allocation allowed in kernel_launch)
__device__ float g_q2[NSTEPS * NTID];   // per-(t, grid, mul) discharge [t][tid]
__device__ float g_w[LENF * NGRID];     // gamma weights [k][g]

__device__ __forceinline__ float flg2(float x) {
    float y; asm("lg2.approx.f32 %0, %1;" : "=f"(y) : "f"(x)); return y;
}
__device__ __forceinline__ float fex2(float x) {
    float y; asm("ex2.approx.f32 %0, %1;" : "=f"(y) : "f"(x)); return y;
}

// ---------------------------------------------------------------------------
// Stage 1: HBV scan. One thread per (grid, mul); 32 blocks x 128 threads
// (proven fast config). Two-phase U=8 body: snow phase fills win[8] (short
// SP/MW chain), then soil/zones phase consumes it — the snow instructions
// provide schedulable filler for the long soil-chain stalls.
// ---------------------------------------------------------------------------
__global__ void __launch_bounds__(128, 1) hbv_scan_kernel(
    const float* __restrict__ prcp,
    const float* __restrict__ tmean,
    const float* __restrict__ pet,
    const float* __restrict__ phy)
{
    const int tid = blockIdx.x * 128 + threadIdx.x;   // 0..4095
    const int g = tid >> 1;
    const int m = tid & 1;

    const float lbv[19] = {1.0f, 50.0f, 0.05f, 0.01f, 0.001f, 0.2f, 0.0f, 0.0f,
                           -2.5f, 0.5f, 0.0f, 0.0f, 0.3f, 0.0f, 0.0f, 0.0f,
                           5.0f/DTC, 0.0f, 0.5f};
    const float ubv[19] = {6.0f, 1000.0f, 0.9f, 0.5f, 0.2f, 1.0f, 10.0f, 100.0f,
                           2.5f, 10.0f, 0.1f, 0.2f, 5.0f, 1.0f, 20.0f, 2500.0f,
                           120.0f/DTC, 1.0f, 5.0f};
    float pp[19];
#pragma unroll
    for (int i = 0; i < 19; i++) {
        float r = phy[g * (19 * NMUL) + i * NMUL + m];
        pp[i] = lbv[i] + r * (ubv[i] - lbv[i]);
    }
    const float BETA   = pp[0];
    const float FC     = pp[1];
    const float CFR    = pp[10];
    const float CWH    = pp[11];
    const float BETAET = pp[12];
    const float Cc     = pp[13];
    const float ALPHA  = pp[18];

    const float invFC       = 1.0f / FC;
    const float k0dt        = pp[2] * DTC;
    const float k1dt        = pp[3] * DTC;
    const float k2dt        = pp[4] * DTC;
    const float percdt      = pp[6] * DTC;
    const float cfmaxdt     = pp[9] * DTC;
    const float f0dt        = pp[16] * DTC;
    const float fmin_f0dt   = pp[17] * f0dt;
    const float omfmin_f0dt = (1.0f - pp[17]) * f0dt;
    const float evap_c      = BETAET * flg2(1.0f / (pp[5] * FC));
    const float eFCc        = fminf(fex2(BETAET * flg2(1.0f / pp[5])), 1.0f);
    const float mpc         = cfmaxdt * pp[8];   // cfmaxdt*TT
    const float ck0         = 1.0f - k0dt;
    const float k0uzl       = k0dt * pp[7];
    const float c1          = 1.0f - k1dt;
    const float c2          = 1.0f - k2dt;
    const float cc2         = Cc * c2;

    float SP = 0.001f, MW = 0.001f, SM = 0.001f, SUZ = 0.001f, SLZ = 0.001f;
    float CcSLZ = Cc * 0.001f;

    // snow stage: SP/MW carry only; returns water_in
    auto snow_stage = [&](float P, float T) -> float {
        float mp   = fmaf(cfmaxdt, T, -mpc);           // cfmaxdt*(T-TT)
        float RAIN = (mp >= 0.0f) ? P : 0.0f;
        float SP1  = (SP + P) - RAIN;                  // SP + SNOW
        float s2   = fmaxf(mp, CFR * mp);              // melt or -refreeze slope
        float x    = fminf(fmaxf(s2, -MW), SP1);       // signed transfer
        SP = SP1 - x;
        float MW2    = MW + x;
        float tosoil = fmaxf(fmaf(-CWH, SP, MW2), 0.0f);
        MW = MW2 - tosoil;
        return RAIN + tosoil;
    };

    // soil + zones stage: SM/SUZ/SLZ carry; consumes win, returns Q
    auto soil_stage = [&](float win, float PV) -> float {
        float omr   = fmaxf(fmaf(-invFC, SM, 1.0f), 1e-6f);
        float fcap  = fmaf(omfmin_f0dt, fex2(ALPHA * flg2(omr)), fmin_f0dt);
        float infil = fminf(win, fcap);
        float ratio = SM * invFC;
        float soilw = fminf(fex2(BETA * flg2(ratio)), 1.0f);
        float SM1   = fmaf(infil, 1.0f - soilw, SM);
        float SM2   = fminf(SM1, FC);
        float e1    = fex2(fmaf(flg2(SM1), BETAET, evap_c));  // e_raw(SM1)
        float xe    = fminf(PV * e1, PV * eFCc);              // PV*e(SM2), clipped
        float SM3   = fmaxf(SM2 - xe, 1e-5f);
        float w1    = fmaf(-invFC, SM3, 1.0f);
        float cap   = CcSLZ * w1;
        float inflow = (SM - SM2) + win;     // == rech + excs + surf (exact)
        SM = SM3 + cap;

        float SUZ1 = SUZ + inflow;
        float SUZ2 = fmaxf(SUZ1 - percdt, 0.0f);
        float perc = SUZ1 - SUZ2;
        float SUZ3 = fminf(SUZ2, fmaf(ck0, SUZ2, k0uzl));
        float SUZn = c1 * SUZ3;
        SUZ = SUZn;
        float SLZ1 = (SLZ - cap) + perc;
        float Q2   = k2dt * SLZ1;
        SLZ   = c2 * SLZ1;
        CcSLZ = cc2 * SLZ1;
        return (SUZ2 - SUZn) + Q2;           // Q0+Q1+Q2
    };

    const int U = 8;                     // 8760 % 8 == 0
    float Pb[U], Tb[U], Eb[U];
#pragma unroll
    for (int u = 0; u < U; u++) {
        Pb[u] = prcp [u * NGRID + g];
        Tb[u] = tmean[u * NGRID + g];
        Eb[u] = pet  [u * NGRID + g];
    }

    float* qbase = g_q2 + tid;

    for (int t0 = 0; t0 < NSTEPS - U; t0 += U) {
        float Pn[U], Tn[U], En[U];
        const int t1 = t0 + U;
#pragma unroll
        for (int u = 0; u < U; u++) {
            Pn[u] = prcp [(t1 + u) * NGRID + g];
            Tn[u] = tmean[(t1 + u) * NGRID + g];
            En[u] = pet  [(t1 + u) * NGRID + g];
        }
        // phase 1: all 8 snow stages (short SP/MW chain)
        float win[U];
#pragma unroll
        for (int u = 0; u < U; u++) win[u] = snow_stage(Pb[u], Tb[u]);
        // phase 2: all 8 soil/zones stages (long SM chain; snow ops fill stalls)
#pragma unroll
        for (int u = 0; u < U; u++)
            qbase[(size_t)(t0 + u) * NTID] = soil_stage(win[u], Eb[u]);
#pragma unroll
        for (int u = 0; u < U; u++) { Pb[u] = Pn[u]; Tb[u] = Tn[u]; Eb[u] = En[u]; }
    }
    // peeled last block
    {
        float win[U];
#pragma unroll
        for (int u = 0; u < U; u++) win[u] = snow_stage(Pb[u], Tb[u]);
#pragma unroll
        for (int u = 0; u < U; u++)
            qbase[(size_t)(NSTEPS - U + u) * NTID] = soil_stage(win[u], Eb[u]);
    }
}

// ---------------------------------------------------------------------------
// Stage 2: gamma routing weights, one thread per grid.
// ---------------------------------------------------------------------------
__global__ void __launch_bounds__(128) weights_kernel(const float* __restrict__ distr)
{
    int g = blockIdx.x * blockDim.x + threadIdx.x;
    if (g >= NGRID) return;

    float aa  = fmaxf(distr[g * 3 + 0] * 5.0f,  0.0f) + 0.1f;
    float th  = fmaxf(distr[g * 3 + 1] * 12.0f, 0.0f) + 0.5f;
    float tau = distr[g * 3 + 2] * 48.0f;

    float lga   = lgammaf(aa);
    float lth   = logf(th);
    float invth = 1.0f / th;
    float am1   = aa - 1.0f;

    float ws[LENF];
    float s = 0.0f;
#pragma unroll
    for (int k = 0; k < LENF; k++) {
        float t  = (float)k + 0.5f;
        float ts = fmaxf(t - tau, 0.001f);
        float lw = -lga - aa * lth + am1 * logf(ts) - ts * invth;
        float w  = expf(lw);
        ws[k] = w;
        s += w;
    }
    float inv = 1.0f / s;
#pragma unroll
    for (int k = 0; k < LENF; k++)
        g_w[k * NGRID + g] = ws[k] * inv;
}

// ---------------------------------------------------------------------------
// Stage 3: 72-tap causal FIR. Tile 32 grids x 128 timesteps; 16 outputs per
// thread, mod-16 register rolling window. Mul pair averaged at load (float2).
// ---------------------------------------------------------------------------
#define CONV_GT   32
#define CONV_TT   128
#define CONV_RPT  16
#define CONV_QS   (CONV_TT + LENF - 1)   /* 199 */

__global__ void __launch_bounds__(256) conv_kernel(float* __restrict__ out)
{
    __shared__ float q_sh[CONV_QS][CONV_GT];   // 199 x 32
    __shared__ float w_sh[LENF][CONV_GT];      // 72 x 32

    const int tid   = threadIdx.x;
    const int gbase = blockIdx.x * CONV_GT;
    const int t0    = blockIdx.y * CONV_TT;

    const float2* q2 = reinterpret_cast<const float2*>(g_q2);

    for (int idx = tid; idx < CONV_QS * CONV_GT; idx += 256) {
        int j = idx >> 5, c = idx & 31;
        int tq = t0 - (LENF - 1) + j;
        float v = 0.0f;
        if (tq >= 0 && tq < NSTEPS) {
            float2 p = q2[(size_t)tq * NGRID + gbase + c];
            v = 0.5f * (p.x + p.y);
        }
        q_sh[j][c] = v;
    }
    for (int idx = tid; idx < LENF * CONV_GT; idx += 256) {
        int k = idx >> 5, c = idx & 31;
        w_sh[k][c] = g_w[k * NGRID + gbase + c];
    }
    __syncthreads();

    const int tx   = tid & 31;
    const int ty   = tid >> 5;        // 0..7
    const int trow = ty * CONV_RPT;

    float acc[CONV_RPT];
#pragma unroll
    for (int r = 0; r < CONV_RPT; r++) acc[r] = 0.0f;

    float buf[16];                    // mod-16 register rolling window
#pragma unroll
    for (int i = 0; i < 16; i++)
        buf[(LENF - 1 + i) & 15] = q_sh[trow + LENF - 1 + i][tx];

#pragma unroll
    for (int k = 0; k < LENF; k++) {
        float wv = w_sh[k][tx];
#pragma unroll
        for (int r = 0; r < CONV_RPT; r++)
            acc[r] += wv * buf[(LENF - 1 - k + r) & 15];
        if (k < LENF - 1)
            buf[(LENF - 2 - k) & 15] = q_sh[trow + LENF - 2 - k][tx];
    }

#pragma unroll
    for (int r = 0; r < CONV_RPT; r++) {
        int t = t0 + trow + r;
        if (t < NSTEPS)
            out[t * NGRID + gbase + tx] = acc[r];
    }
}

// ---------------------------------------------------------------------------
extern "C" void kernel_launch(void* const* d_in, const int* in_sizes, int n_in,
                              void* d_out, int out_size)
{
    const float* prcp  = (const float*)d_in[0];
    const float* tmean = (const float*)d_in[1];
    const float* pet   = (const float*)d_in[2];
    const float* phy   = (const float*)d_in[3];
    const float* distr = (const float*)d_in[4];
    float* out = (float*)d_out;

    hbv_scan_kernel<<<NTID / 128, 128>>>(prcp, tmean, pet, phy);
    weights_kernel<<<(NGRID + 127) / 128, 128>>>(distr);

    dim3 gc(NGRID / CONV_GT, (NSTEPS + CONV_TT - 1) / CONV_TT);
    conv_kernel<<<gc, 256>>>(out);
}